// round 5
// baseline (speedup 1.0000x reference)
#include <cuda_runtime.h>

#define C_MLP 32
#define NV    10              // v = (x,y,z,f0..4,cx,cy)
#define NPAIR 55              // upper triangle of 10x10
#define NSTAT 65              // 55 + 10
#define GRID_A 296
#define BLK_A  256
#define PSIZE  0.075f
#define XMIN  -54.0f
#define YMIN  -54.0f
#define CZ    -1.0f
#define BN_EPS 1e-3f
#define MMAX   131072
#define CAP    64
#define NBIN   66             // cnt classes 0..65 (cnt clamped to 64)

typedef unsigned long long u64;

// static scratch
__device__ float  g_part[GRID_A * 72];            // per-block partial stats
__device__ float4 g_A4[NV * 8];                   // folded weights A' (10 x 32)
__device__ float  g_e[C_MLP];                     // folded bias
__device__ int    g_cnt[MMAX];
__device__ int    g_hist[NBIN];
__device__ int    g_off[NBIN];
__device__ int    g_order[MMAX];                  // pillars sorted by cnt
__device__ float4 g_pay[(size_t)MMAX * CAP * 2];  // bucketed payloads (32B/pt)

// ---- f32x2 helpers -------------------------------------------------------
__device__ __forceinline__ u64 ffma2(u64 a, u64 b, u64 c) {
    u64 d;
    asm("fma.rn.f32x2 %0, %1, %2, %3;" : "=l"(d) : "l"(a), "l"(b), "l"(c));
    return d;
}
__device__ __forceinline__ u64 pack2(float x) {
    u64 d; unsigned r = __float_as_uint(x);
    asm("mov.b64 %0, {%1, %1};" : "=l"(d) : "r"(r));
    return d;
}

// ---------------------------------------------------------------------------
__global__ void zero_kernel(int M) {
    int i = blockIdx.x * blockDim.x + threadIdx.x;
    if (i < M) g_cnt[i] = 0;
    if (i < NBIN) g_hist[i] = 0;
}

// ---------------------------------------------------------------------------
// Stage A (fused): stats (10-var sums + second moments) + payload scatter.
// ---------------------------------------------------------------------------
__global__ __launch_bounds__(BLK_A)
void stageA_kernel(const float* __restrict__ xyz,
                   const float* __restrict__ ptf,
                   const int*   __restrict__ pil,
                   const int*   __restrict__ psi,
                   int N)
{
    float acc[NPAIR];
    float s[NV];
#pragma unroll
    for (int j = 0; j < NPAIR; j++) acc[j] = 0.f;
#pragma unroll
    for (int j = 0; j < NV; j++) s[j] = 0.f;

    const int stride = GRID_A * BLK_A;
    for (int i = blockIdx.x * BLK_A + threadIdx.x; i < N; i += stride) {
        int p  = psi[i];
        int py = pil[3 * p + 1];
        int px = pil[3 * p + 2];
        float v[NV];
        v[0] = xyz[3 * i + 0];
        v[1] = xyz[3 * i + 1];
        v[2] = xyz[3 * i + 2];
#pragma unroll
        for (int k = 0; k < 5; k++) v[3 + k] = ptf[5 * i + k];
        v[8] = ((float)px + 0.5f) * PSIZE + XMIN;
        v[9] = ((float)py + 0.5f) * PSIZE + YMIN;

        int pos = atomicAdd(&g_cnt[p], 1);
        if (pos < CAP) {
            size_t base = ((size_t)p * CAP + pos) * 2;
            g_pay[base]     = make_float4(v[0], v[1], v[2], v[3]);
            g_pay[base + 1] = make_float4(v[4], v[5], v[6], v[7]);
        }

        int j = 0;
#pragma unroll
        for (int a = 0; a < NV; a++) {
            s[a] += v[a];
#pragma unroll
            for (int b = a; b < NV; b++) {
                acc[j] = fmaf(v[a], v[b], acc[j]);
                j++;
            }
        }
    }

#pragma unroll
    for (int j = 0; j < NPAIR; j++) {
        float t = acc[j];
        t += __shfl_xor_sync(0xffffffffu, t, 16);
        t += __shfl_xor_sync(0xffffffffu, t, 8);
        t += __shfl_xor_sync(0xffffffffu, t, 4);
        t += __shfl_xor_sync(0xffffffffu, t, 2);
        t += __shfl_xor_sync(0xffffffffu, t, 1);
        acc[j] = t;
    }
#pragma unroll
    for (int j = 0; j < NV; j++) {
        float t = s[j];
        t += __shfl_xor_sync(0xffffffffu, t, 16);
        t += __shfl_xor_sync(0xffffffffu, t, 8);
        t += __shfl_xor_sync(0xffffffffu, t, 4);
        t += __shfl_xor_sync(0xffffffffu, t, 2);
        t += __shfl_xor_sync(0xffffffffu, t, 1);
        s[j] = t;
    }

    __shared__ float sm[BLK_A / 32][NSTAT];
    int lane = threadIdx.x & 31;
    int wid  = threadIdx.x >> 5;
    if (lane == 0) {
#pragma unroll
        for (int j = 0; j < NPAIR; j++) sm[wid][j] = acc[j];
#pragma unroll
        for (int j = 0; j < NV; j++) sm[wid][NPAIR + j] = s[j];
    }
    __syncthreads();
    if (threadIdx.x < NSTAT) {
        float t = 0.f;
#pragma unroll
        for (int w = 0; w < BLK_A / 32; w++) t += sm[w][threadIdx.x];
        g_part[blockIdx.x * 72 + threadIdx.x] = t;
    }
}

// ---------------------------------------------------------------------------
// Counting sort of pillars by cnt: histogram -> scan -> scatter
// ---------------------------------------------------------------------------
__global__ void hist_kernel(int M) {
    int i = blockIdx.x * blockDim.x + threadIdx.x;
    if (i < M) {
        int c = g_cnt[i]; if (c > CAP) c = CAP;
        atomicAdd(&g_hist[c], 1);
    }
}
__global__ void scan_kernel() {
    __shared__ int sh[NBIN];
    int t = threadIdx.x;                       // 128 threads
    if (t < NBIN) sh[t] = g_hist[t];
    __syncthreads();
    if (t == 0) {
        int run = 0;
#pragma unroll
        for (int i = 0; i < NBIN; i++) { int v = sh[i]; sh[i] = run; run += v; }
    }
    __syncthreads();
    if (t < NBIN) g_off[t] = sh[t];
}
__global__ void order_kernel(int M) {
    int i = blockIdx.x * blockDim.x + threadIdx.x;
    if (i < M) {
        int c = g_cnt[i]; if (c > CAP) c = CAP;
        int pos = atomicAdd(&g_off[c], 1);
        g_order[pos] = i;
    }
}

// ---------------------------------------------------------------------------
// Stage B: reduce partials; fold BN into weights A' (10x32) and bias e.
// ---------------------------------------------------------------------------
__global__ void stageB_kernel(const float* __restrict__ W,
                              const float* __restrict__ gamma,
                              const float* __restrict__ beta,
                              int N)
{
    __shared__ float red[NSTAT];
    int t = threadIdx.x;           // 96 threads
    if (t < NSTAT) {
        float a0 = 0.f, a1 = 0.f, a2 = 0.f, a3 = 0.f;
        int b = 0;
        for (; b + 4 <= GRID_A; b += 4) {
            a0 += g_part[(b + 0) * 72 + t];
            a1 += g_part[(b + 1) * 72 + t];
            a2 += g_part[(b + 2) * 72 + t];
            a3 += g_part[(b + 3) * 72 + t];
        }
        for (; b < GRID_A; b++) a0 += g_part[b * 72 + t];
        red[t] = (a0 + a1) + (a2 + a3);
    }
    __syncthreads();
    if (t < C_MLP) {
        float w[11];
#pragma unroll
        for (int k = 0; k < 11; k++) w[k] = W[k * C_MLP + t];
        float a[NV];
        a[0] = w[0] + w[3];
        a[1] = w[1] + w[4];
        a[2] = w[2] + w[5];
#pragma unroll
        for (int k = 0; k < 5; k++) a[3 + k] = w[6 + k];
        a[8] = -w[0];
        a[9] = -w[1];
        float bb = -CZ * w[2];

        const float invN = 1.0f / (float)N;
        float mva = 0.f;
#pragma unroll
        for (int k = 0; k < NV; k++) mva = fmaf(a[k], red[NPAIR + k] * invN, mva);

        float quad = 0.f;
        int j = 0;
#pragma unroll
        for (int p = 0; p < NV; p++) {
            quad = fmaf(a[p] * a[p], red[j], quad);  j++;
#pragma unroll
            for (int q = p + 1; q < NV; q++) {
                quad = fmaf(2.f * a[p] * a[q], red[j], quad);  j++;
            }
        }
        quad *= invN;

        float mean = mva + bb;
        float ex2  = quad + 2.f * bb * mva + bb * bb;
        float var  = ex2 - mean * mean;
        float sc   = gamma[t] * rsqrtf(var + BN_EPS);

        float* A = (float*)g_A4;
#pragma unroll
        for (int k = 0; k < NV; k++) A[k * C_MLP + t] = sc * a[k];
        g_e[t] = beta[t] - sc * mva;
    }
}

// ---------------------------------------------------------------------------
// Pool: lane = pillar (taken in cnt-sorted order -> near-zero warp skew).
// 16 packed f32x2 accumulators; inner loop = 8k x (1 LDS.v2.u64 x8 + 16 FFMA2).
// Per-pillar constant d and the ReLU are applied once after the max loop:
// max_p(dot+d) = max_p(dot)+d; init -inf also makes empty pillars -> 0.
// ---------------------------------------------------------------------------
__global__ __launch_bounds__(256)
void pool_kernel(const int* __restrict__ pil,
                 float* __restrict__ out,
                 int M)
{
    __shared__ __align__(16) u64 As2[NV * 16];   // A' as packed f32x2
    __shared__ float es[C_MLP];
    if (threadIdx.x < NV * 16) As2[threadIdx.x] = ((const u64*)g_A4)[threadIdx.x];
    if (threadIdx.x >= 192 && threadIdx.x < 224) es[threadIdx.x - 192] = g_e[threadIdx.x - 192];
    __syncthreads();

    int gid = blockIdx.x * blockDim.x + threadIdx.x;
    if (gid >= M) return;
    int p = g_order[gid];
    int cnt = g_cnt[p];
    if (cnt > CAP) cnt = CAP;

    unsigned as_base;
    asm("{ .reg .u64 t; cvta.to.shared.u64 t, %1; cvt.u32.u64 %0, t; }"
        : "=r"(as_base) : "l"(As2));

    const float NEG_INF = __int_as_float(0xff800000);
    float m[C_MLP];
#pragma unroll
    for (int u = 0; u < C_MLP; u++) m[u] = NEG_INF;

    const float4* pay = g_pay + (size_t)p * CAP * 2;
    for (int j = 0; j < cnt; j++) {
        float4 va = __ldg(&pay[2 * j]);
        float4 vb = __ldg(&pay[2 * j + 1]);
        float vv[8] = {va.x, va.y, va.z, va.w, vb.x, vb.y, vb.z, vb.w};

        u64 hv[16];
#pragma unroll
        for (int q = 0; q < 16; q++) hv[q] = 0ull;

#pragma unroll
        for (int k = 0; k < 8; k++) {
            u64 gkk = pack2(vv[k]);
            unsigned row = as_base + k * 128;
#pragma unroll
            for (int q = 0; q < 8; q++) {
                u64 w0, w1;
                asm("ld.shared.v2.u64 {%0, %1}, [%2];"
                    : "=l"(w0), "=l"(w1) : "r"(row + q * 16));
                hv[2 * q]     = ffma2(gkk, w0, hv[2 * q]);
                hv[2 * q + 1] = ffma2(gkk, w1, hv[2 * q + 1]);
            }
        }
#pragma unroll
        for (int q = 0; q < 16; q++) {
            float lo, hi;
            asm("mov.b64 {%0, %1}, %2;" : "=f"(lo), "=f"(hi) : "l"(hv[q]));
            m[2 * q]     = fmaxf(m[2 * q],     lo);
            m[2 * q + 1] = fmaxf(m[2 * q + 1], hi);
        }
    }

    float cx = ((float)pil[3 * p + 2] + 0.5f) * PSIZE + XMIN;
    float cy = ((float)pil[3 * p + 1] + 0.5f) * PSIZE + YMIN;
    const float* Asf = (const float*)As2;   // row k at Asf[k*32 + c]

    float4* o = (float4*)(out + (size_t)p * C_MLP);
#pragma unroll
    for (int q = 0; q < 8; q++) {
        float4 r;
        float d0 = fmaf(cx, Asf[256 + 4 * q + 0], fmaf(cy, Asf[288 + 4 * q + 0], es[4 * q + 0]));
        float d1 = fmaf(cx, Asf[256 + 4 * q + 1], fmaf(cy, Asf[288 + 4 * q + 1], es[4 * q + 1]));
        float d2 = fmaf(cx, Asf[256 + 4 * q + 2], fmaf(cy, Asf[288 + 4 * q + 2], es[4 * q + 2]));
        float d3 = fmaf(cx, Asf[256 + 4 * q + 3], fmaf(cy, Asf[288 + 4 * q + 3], es[4 * q + 3]));
        r.x = fmaxf(m[4 * q + 0] + d0, 0.f);
        r.y = fmaxf(m[4 * q + 1] + d1, 0.f);
        r.z = fmaxf(m[4 * q + 2] + d2, 0.f);
        r.w = fmaxf(m[4 * q + 3] + d3, 0.f);
        o[q] = r;
    }
}

// ---------------------------------------------------------------------------
extern "C" void kernel_launch(void* const* d_in, const int* in_sizes, int n_in,
                              void* d_out, int out_size)
{
    const float* xyz   = (const float*)d_in[0];   // (N,3)
    const float* ptf   = (const float*)d_in[1];   // (N,5)
    const float* W1    = (const float*)d_in[2];   // (11,32)
    const float* gamma = (const float*)d_in[3];   // (32)
    const float* beta  = (const float*)d_in[4];   // (32)
    const int*   pil   = (const int*)d_in[5];     // (M,3)
    const int*   psi   = (const int*)d_in[6];     // (N)
    int N = in_sizes[6];
    int M = in_sizes[5] / 3;
    float* out = (float*)d_out;                   // (M,32)

    zero_kernel<<<(M + 255) / 256, 256>>>(M);
    stageA_kernel<<<GRID_A, BLK_A>>>(xyz, ptf, pil, psi, N);
    hist_kernel<<<(M + 255) / 256, 256>>>(M);
    scan_kernel<<<1, 128>>>();
    order_kernel<<<(M + 255) / 256, 256>>>(M);
    stageB_kernel<<<1, 96>>>(W1, gamma, beta, N);
    pool_kernel<<<(M + 255) / 256, 256>>>(pil, out, M);
}

// round 6
// speedup vs baseline: 1.4848x; 1.4848x over previous
#include <cuda_runtime.h>

#define C_MLP 32
#define NV    10              // v = (x,y,z,f0..4,cx,cy)
#define NPAIR 55              // upper triangle of 10x10
#define NSTAT 65              // 55 + 10
#define GRID_A 296
#define BLK_A  256
#define PSIZE  0.075f
#define XMIN  -54.0f
#define YMIN  -54.0f
#define CZ    -1.0f
#define BN_EPS 1e-3f
#define MMAX   131072
#define CAP    64

// static scratch
__device__ float  g_part[GRID_A * 72];            // per-block partial stats
__device__ float  g_A[NV * C_MLP];                // folded weights A' (10 x 32)
__device__ float  g_e[C_MLP];                     // folded bias
__device__ int    g_cnt[MMAX];
__device__ float4 g_pay[(size_t)MMAX * CAP * 2];  // bucketed payloads (32B/pt)

// ---------------------------------------------------------------------------
__global__ void zero_kernel(int M) {
    int i = blockIdx.x * blockDim.x + threadIdx.x;
    if (i < M) g_cnt[i] = 0;
}

// ---------------------------------------------------------------------------
// Scatter: bucket each point's 32B payload (x,y,z,f0..f4) into its pillar.
// Lean kernel: coalesced reads, scattered STG.128 pair, one atomic.
// ---------------------------------------------------------------------------
__global__ __launch_bounds__(256)
void scatter_kernel(const float* __restrict__ xyz,
                    const float* __restrict__ ptf,
                    const int*   __restrict__ psi,
                    int N)
{
    int i = blockIdx.x * blockDim.x + threadIdx.x;
    if (i >= N) return;
    int p = psi[i];
    float x  = xyz[3 * i + 0];
    float y  = xyz[3 * i + 1];
    float z  = xyz[3 * i + 2];
    float f0 = ptf[5 * i + 0];
    float f1 = ptf[5 * i + 1];
    float f2 = ptf[5 * i + 2];
    float f3 = ptf[5 * i + 3];
    float f4 = ptf[5 * i + 4];
    int pos = atomicAdd(&g_cnt[p], 1);
    if (pos < CAP) {
        size_t base = ((size_t)p * CAP + pos) * 2;
        g_pay[base]     = make_float4(x, y, z, f0);
        g_pay[base + 1] = make_float4(f1, f2, f3, f4);
    }
}

// ---------------------------------------------------------------------------
// Stats: sums + second moments of v = (x,y,z,f0..4,cx,cy). Pure compute,
// coalesced point reads, pil gather (1.4MB, L2-resident).
// ---------------------------------------------------------------------------
__global__ __launch_bounds__(BLK_A)
void stats_kernel(const float* __restrict__ xyz,
                  const float* __restrict__ ptf,
                  const int*   __restrict__ pil,
                  const int*   __restrict__ psi,
                  int N)
{
    float acc[NPAIR];
    float s[NV];
#pragma unroll
    for (int j = 0; j < NPAIR; j++) acc[j] = 0.f;
#pragma unroll
    for (int j = 0; j < NV; j++) s[j] = 0.f;

    const int stride = GRID_A * BLK_A;
    for (int i = blockIdx.x * BLK_A + threadIdx.x; i < N; i += stride) {
        int p  = psi[i];
        int py = pil[3 * p + 1];
        int px = pil[3 * p + 2];
        float v[NV];
        v[0] = xyz[3 * i + 0];
        v[1] = xyz[3 * i + 1];
        v[2] = xyz[3 * i + 2];
#pragma unroll
        for (int k = 0; k < 5; k++) v[3 + k] = ptf[5 * i + k];
        v[8] = ((float)px + 0.5f) * PSIZE + XMIN;
        v[9] = ((float)py + 0.5f) * PSIZE + YMIN;

        int j = 0;
#pragma unroll
        for (int a = 0; a < NV; a++) {
            s[a] += v[a];
#pragma unroll
            for (int b = a; b < NV; b++) {
                acc[j] = fmaf(v[a], v[b], acc[j]);
                j++;
            }
        }
    }

#pragma unroll
    for (int j = 0; j < NPAIR; j++) {
        float t = acc[j];
        t += __shfl_xor_sync(0xffffffffu, t, 16);
        t += __shfl_xor_sync(0xffffffffu, t, 8);
        t += __shfl_xor_sync(0xffffffffu, t, 4);
        t += __shfl_xor_sync(0xffffffffu, t, 2);
        t += __shfl_xor_sync(0xffffffffu, t, 1);
        acc[j] = t;
    }
#pragma unroll
    for (int j = 0; j < NV; j++) {
        float t = s[j];
        t += __shfl_xor_sync(0xffffffffu, t, 16);
        t += __shfl_xor_sync(0xffffffffu, t, 8);
        t += __shfl_xor_sync(0xffffffffu, t, 4);
        t += __shfl_xor_sync(0xffffffffu, t, 2);
        t += __shfl_xor_sync(0xffffffffu, t, 1);
        s[j] = t;
    }

    __shared__ float sm[BLK_A / 32][NSTAT];
    int lane = threadIdx.x & 31;
    int wid  = threadIdx.x >> 5;
    if (lane == 0) {
#pragma unroll
        for (int j = 0; j < NPAIR; j++) sm[wid][j] = acc[j];
#pragma unroll
        for (int j = 0; j < NV; j++) sm[wid][NPAIR + j] = s[j];
    }
    __syncthreads();
    if (threadIdx.x < NSTAT) {
        float t = 0.f;
#pragma unroll
        for (int w = 0; w < BLK_A / 32; w++) t += sm[w][threadIdx.x];
        g_part[blockIdx.x * 72 + threadIdx.x] = t;
    }
}

// ---------------------------------------------------------------------------
// Stage B: reduce partials; fold BN into weights A' (10x32) and bias e.
// ---------------------------------------------------------------------------
__global__ void stageB_kernel(const float* __restrict__ W,
                              const float* __restrict__ gamma,
                              const float* __restrict__ beta,
                              int N)
{
    __shared__ float red[NSTAT];
    int t = threadIdx.x;           // 96 threads
    if (t < NSTAT) {
        float a0 = 0.f, a1 = 0.f, a2 = 0.f, a3 = 0.f;
        int b = 0;
        for (; b + 4 <= GRID_A; b += 4) {
            a0 += g_part[(b + 0) * 72 + t];
            a1 += g_part[(b + 1) * 72 + t];
            a2 += g_part[(b + 2) * 72 + t];
            a3 += g_part[(b + 3) * 72 + t];
        }
        for (; b < GRID_A; b++) a0 += g_part[b * 72 + t];
        red[t] = (a0 + a1) + (a2 + a3);
    }
    __syncthreads();
    if (t < C_MLP) {
        float w[11];
#pragma unroll
        for (int k = 0; k < 11; k++) w[k] = W[k * C_MLP + t];
        float a[NV];
        a[0] = w[0] + w[3];
        a[1] = w[1] + w[4];
        a[2] = w[2] + w[5];
#pragma unroll
        for (int k = 0; k < 5; k++) a[3 + k] = w[6 + k];
        a[8] = -w[0];
        a[9] = -w[1];
        float bb = -CZ * w[2];

        const float invN = 1.0f / (float)N;
        float mva = 0.f;
#pragma unroll
        for (int k = 0; k < NV; k++) mva = fmaf(a[k], red[NPAIR + k] * invN, mva);

        float quad = 0.f;
        int j = 0;
#pragma unroll
        for (int p = 0; p < NV; p++) {
            quad = fmaf(a[p] * a[p], red[j], quad);  j++;
#pragma unroll
            for (int q = p + 1; q < NV; q++) {
                quad = fmaf(2.f * a[p] * a[q], red[j], quad);  j++;
            }
        }
        quad *= invN;

        float mean = mva + bb;
        float ex2  = quad + 2.f * bb * mva + bb * bb;
        float var  = ex2 - mean * mean;
        float sc   = gamma[t] * rsqrtf(var + BN_EPS);

#pragma unroll
        for (int k = 0; k < NV; k++) g_A[k * C_MLP + t] = sc * a[k];
        g_e[t] = beta[t] - sc * mva;
    }
}

// ---------------------------------------------------------------------------
// Pool: WARP = PILLAR, LANE = CHANNEL. Lane's 8 weights live in registers;
// point payload arrives via uniform-address LDG.128 broadcast (same 32B for
// all lanes). Zero LDS in the loop, zero warp skew. Per-pillar constant
// d = cx*a8 + cy*a9 + e and ReLU applied once after the max loop
// (max_j(dot_j + d) = max_j(dot_j) + d; m init -inf makes empty pillars 0).
// ---------------------------------------------------------------------------
__global__ __launch_bounds__(256)
void pool_kernel(const int* __restrict__ pil,
                 float* __restrict__ out,
                 int M)
{
    int wid  = threadIdx.x >> 5;
    int lane = threadIdx.x & 31;
    int p    = blockIdx.x * 8 + wid;
    if (p >= M) return;

    // lane's weight column (registers, loaded once, coalesced across lanes)
    float w0 = g_A[0 * C_MLP + lane];
    float w1 = g_A[1 * C_MLP + lane];
    float w2 = g_A[2 * C_MLP + lane];
    float w3 = g_A[3 * C_MLP + lane];
    float w4 = g_A[4 * C_MLP + lane];
    float w5 = g_A[5 * C_MLP + lane];
    float w6 = g_A[6 * C_MLP + lane];
    float w7 = g_A[7 * C_MLP + lane];
    float a8 = g_A[8 * C_MLP + lane];
    float a9 = g_A[9 * C_MLP + lane];
    float e  = g_e[lane];

    int cnt = g_cnt[p];
    if (cnt > CAP) cnt = CAP;

    const float4* pay = g_pay + (size_t)p * CAP * 2;
    float m = __int_as_float(0xff800000);   // -inf

    int j = 0;
    for (; j + 2 <= cnt; j += 2) {
        float4 va0 = __ldg(&pay[2 * j]);
        float4 vb0 = __ldg(&pay[2 * j + 1]);
        float4 va1 = __ldg(&pay[2 * j + 2]);
        float4 vb1 = __ldg(&pay[2 * j + 3]);
        float h0 = va0.x * w0;
        float h1 = va1.x * w0;
        h0 = fmaf(va0.y, w1, h0);  h1 = fmaf(va1.y, w1, h1);
        h0 = fmaf(va0.z, w2, h0);  h1 = fmaf(va1.z, w2, h1);
        h0 = fmaf(va0.w, w3, h0);  h1 = fmaf(va1.w, w3, h1);
        h0 = fmaf(vb0.x, w4, h0);  h1 = fmaf(vb1.x, w4, h1);
        h0 = fmaf(vb0.y, w5, h0);  h1 = fmaf(vb1.y, w5, h1);
        h0 = fmaf(vb0.z, w6, h0);  h1 = fmaf(vb1.z, w6, h1);
        h0 = fmaf(vb0.w, w7, h0);  h1 = fmaf(vb1.w, w7, h1);
        m = fmaxf(m, fmaxf(h0, h1));
    }
    if (j < cnt) {
        float4 va = __ldg(&pay[2 * j]);
        float4 vb = __ldg(&pay[2 * j + 1]);
        float h = va.x * w0;
        h = fmaf(va.y, w1, h);
        h = fmaf(va.z, w2, h);
        h = fmaf(va.w, w3, h);
        h = fmaf(vb.x, w4, h);
        h = fmaf(vb.y, w5, h);
        h = fmaf(vb.z, w6, h);
        h = fmaf(vb.w, w7, h);
        m = fmaxf(m, h);
    }

    float cx = ((float)pil[3 * p + 2] + 0.5f) * PSIZE + XMIN;
    float cy = ((float)pil[3 * p + 1] + 0.5f) * PSIZE + YMIN;
    float d  = fmaf(cx, a8, fmaf(cy, a9, e));
    out[(size_t)p * C_MLP + lane] = fmaxf(m + d, 0.f);
}

// ---------------------------------------------------------------------------
extern "C" void kernel_launch(void* const* d_in, const int* in_sizes, int n_in,
                              void* d_out, int out_size)
{
    const float* xyz   = (const float*)d_in[0];   // (N,3)
    const float* ptf   = (const float*)d_in[1];   // (N,5)
    const float* W1    = (const float*)d_in[2];   // (11,32)
    const float* gamma = (const float*)d_in[3];   // (32)
    const float* beta  = (const float*)d_in[4];   // (32)
    const int*   pil   = (const int*)d_in[5];     // (M,3)
    const int*   psi   = (const int*)d_in[6];     // (N)
    int N = in_sizes[6];
    int M = in_sizes[5] / 3;
    float* out = (float*)d_out;                   // (M,32)

    zero_kernel<<<(M + 255) / 256, 256>>>(M);
    scatter_kernel<<<(N + 255) / 256, 256>>>(xyz, ptf, psi, N);
    stats_kernel<<<GRID_A, BLK_A>>>(xyz, ptf, pil, psi, N);
    stageB_kernel<<<1, 96>>>(W1, gamma, beta, N);
    pool_kernel<<<(M + 7) / 8, 256>>>(pil, out, M);
}

// round 7
// speedup vs baseline: 1.6319x; 1.0991x over previous
#include <cuda_runtime.h>

#define C_MLP 32
#define NV    10              // v = (x,y,z,f0..4,cx,cy)
#define NPAIR 55              // upper triangle of 10x10
#define NSTAT 65              // 55 + 10
#define GRID_A 296
#define BLK_A  256
#define NSLICE 15             // stageB reduction slices
#define PSIZE  0.075f
#define XMIN  -54.0f
#define YMIN  -54.0f
#define CZ    -1.0f
#define BN_EPS 1e-3f
#define MMAX   131072
#define CAP    64

// static scratch (BSS zero-init; g_cnt is kept zeroed by pool_kernel)
__device__ float  g_part[GRID_A * 72];            // per-block partial stats
__device__ float  g_A[NV * C_MLP];                // folded weights A' (10 x 32)
__device__ float  g_e[C_MLP];                     // folded bias
__device__ int    g_cnt[MMAX];
__device__ float4 g_pay[(size_t)MMAX * CAP * 2];  // bucketed payloads (32B/pt)

// ---------------------------------------------------------------------------
// Scatter: bucket each point's 32B payload (x,y,z,f0..f4) into its pillar.
// g_cnt starts at zero (BSS on first call; reset by pool_kernel thereafter).
// ---------------------------------------------------------------------------
__global__ __launch_bounds__(256)
void scatter_kernel(const float* __restrict__ xyz,
                    const float* __restrict__ ptf,
                    const int*   __restrict__ psi,
                    int N)
{
    int i = blockIdx.x * blockDim.x + threadIdx.x;
    if (i >= N) return;
    int p = psi[i];
    float x  = xyz[3 * i + 0];
    float y  = xyz[3 * i + 1];
    float z  = xyz[3 * i + 2];
    float f0 = ptf[5 * i + 0];
    float f1 = ptf[5 * i + 1];
    float f2 = ptf[5 * i + 2];
    float f3 = ptf[5 * i + 3];
    float f4 = ptf[5 * i + 4];
    int pos = atomicAdd(&g_cnt[p], 1);
    if (pos < CAP) {
        size_t base = ((size_t)p * CAP + pos) * 2;
        g_pay[base]     = make_float4(x, y, z, f0);
        g_pay[base + 1] = make_float4(f1, f2, f3, f4);
    }
}

// ---------------------------------------------------------------------------
// Stats: sums + second moments of v = (x,y,z,f0..4,cx,cy).
// ---------------------------------------------------------------------------
__global__ __launch_bounds__(BLK_A)
void stats_kernel(const float* __restrict__ xyz,
                  const float* __restrict__ ptf,
                  const int*   __restrict__ pil,
                  const int*   __restrict__ psi,
                  int N)
{
    float acc[NPAIR];
    float s[NV];
#pragma unroll
    for (int j = 0; j < NPAIR; j++) acc[j] = 0.f;
#pragma unroll
    for (int j = 0; j < NV; j++) s[j] = 0.f;

    const int stride = GRID_A * BLK_A;
    for (int i = blockIdx.x * BLK_A + threadIdx.x; i < N; i += stride) {
        int p  = psi[i];
        int py = pil[3 * p + 1];
        int px = pil[3 * p + 2];
        float v[NV];
        v[0] = xyz[3 * i + 0];
        v[1] = xyz[3 * i + 1];
        v[2] = xyz[3 * i + 2];
#pragma unroll
        for (int k = 0; k < 5; k++) v[3 + k] = ptf[5 * i + k];
        v[8] = ((float)px + 0.5f) * PSIZE + XMIN;
        v[9] = ((float)py + 0.5f) * PSIZE + YMIN;

        int j = 0;
#pragma unroll
        for (int a = 0; a < NV; a++) {
            s[a] += v[a];
#pragma unroll
            for (int b = a; b < NV; b++) {
                acc[j] = fmaf(v[a], v[b], acc[j]);
                j++;
            }
        }
    }

#pragma unroll
    for (int j = 0; j < NPAIR; j++) {
        float t = acc[j];
        t += __shfl_xor_sync(0xffffffffu, t, 16);
        t += __shfl_xor_sync(0xffffffffu, t, 8);
        t += __shfl_xor_sync(0xffffffffu, t, 4);
        t += __shfl_xor_sync(0xffffffffu, t, 2);
        t += __shfl_xor_sync(0xffffffffu, t, 1);
        acc[j] = t;
    }
#pragma unroll
    for (int j = 0; j < NV; j++) {
        float t = s[j];
        t += __shfl_xor_sync(0xffffffffu, t, 16);
        t += __shfl_xor_sync(0xffffffffu, t, 8);
        t += __shfl_xor_sync(0xffffffffu, t, 4);
        t += __shfl_xor_sync(0xffffffffu, t, 2);
        t += __shfl_xor_sync(0xffffffffu, t, 1);
        s[j] = t;
    }

    __shared__ float sm[BLK_A / 32][NSTAT];
    int lane = threadIdx.x & 31;
    int wid  = threadIdx.x >> 5;
    if (lane == 0) {
#pragma unroll
        for (int j = 0; j < NPAIR; j++) sm[wid][j] = acc[j];
#pragma unroll
        for (int j = 0; j < NV; j++) sm[wid][NPAIR + j] = s[j];
    }
    __syncthreads();
    if (threadIdx.x < NSTAT) {
        float t = 0.f;
#pragma unroll
        for (int w = 0; w < BLK_A / 32; w++) t += sm[w][threadIdx.x];
        g_part[blockIdx.x * 72 + threadIdx.x] = t;
    }
}

// ---------------------------------------------------------------------------
// Stage B: PARALLEL reduce of 296x65 partials (15 slices x 65 stats across
// 1024 threads), then fold BN into weights A' and bias e.
// ---------------------------------------------------------------------------
__global__ __launch_bounds__(1024)
void stageB_kernel(const float* __restrict__ W,
                   const float* __restrict__ gamma,
                   const float* __restrict__ beta,
                   int N)
{
    __shared__ float tmp[NSLICE][NSTAT + 1];
    __shared__ float red[NSTAT];
    int slice = threadIdx.x / NSTAT;     // 0..15 (use 0..14)
    int stat  = threadIdx.x % NSTAT;
    if (slice < NSLICE) {
        float a0 = 0.f, a1 = 0.f, a2 = 0.f, a3 = 0.f;
        int b = slice;
        for (; b + 3 * NSLICE < GRID_A; b += 4 * NSLICE) {
            a0 += g_part[(b + 0 * NSLICE) * 72 + stat];
            a1 += g_part[(b + 1 * NSLICE) * 72 + stat];
            a2 += g_part[(b + 2 * NSLICE) * 72 + stat];
            a3 += g_part[(b + 3 * NSLICE) * 72 + stat];
        }
        for (; b < GRID_A; b += NSLICE) a0 += g_part[b * 72 + stat];
        tmp[slice][stat] = (a0 + a1) + (a2 + a3);
    }
    __syncthreads();
    int t = threadIdx.x;
    if (t < NSTAT) {
        float a = 0.f;
#pragma unroll
        for (int sl = 0; sl < NSLICE; sl++) a += tmp[sl][t];
        red[t] = a;
    }
    __syncthreads();
    if (t < C_MLP) {
        float w[11];
#pragma unroll
        for (int k = 0; k < 11; k++) w[k] = W[k * C_MLP + t];
        float a[NV];
        a[0] = w[0] + w[3];
        a[1] = w[1] + w[4];
        a[2] = w[2] + w[5];
#pragma unroll
        for (int k = 0; k < 5; k++) a[3 + k] = w[6 + k];
        a[8] = -w[0];
        a[9] = -w[1];
        float bb = -CZ * w[2];

        const float invN = 1.0f / (float)N;
        float mva = 0.f;
#pragma unroll
        for (int k = 0; k < NV; k++) mva = fmaf(a[k], red[NPAIR + k] * invN, mva);

        float quad = 0.f;
        int j = 0;
#pragma unroll
        for (int p = 0; p < NV; p++) {
            quad = fmaf(a[p] * a[p], red[j], quad);  j++;
#pragma unroll
            for (int q = p + 1; q < NV; q++) {
                quad = fmaf(2.f * a[p] * a[q], red[j], quad);  j++;
            }
        }
        quad *= invN;

        float mean = mva + bb;
        float ex2  = quad + 2.f * bb * mva + bb * bb;
        float var  = ex2 - mean * mean;
        float sc   = gamma[t] * rsqrtf(var + BN_EPS);

#pragma unroll
        for (int k = 0; k < NV; k++) g_A[k * C_MLP + t] = sc * a[k];
        g_e[t] = beta[t] - sc * mva;
    }
}

// ---------------------------------------------------------------------------
// Pool: WARP = PILLAR, LANE = CHANNEL. Lane's weights in registers; point
// payload via uniform-address LDG.128 broadcast. Zero LDS, zero warp skew.
// d = cx*a8 + cy*a9 + e and ReLU applied once after the max loop.
// Also RESETS g_cnt[p] = 0 so the next kernel_launch call starts clean
// (replaces the zero kernel; deterministic across graph replays).
// ---------------------------------------------------------------------------
__global__ __launch_bounds__(256)
void pool_kernel(const int* __restrict__ pil,
                 float* __restrict__ out,
                 int M)
{
    int wid  = threadIdx.x >> 5;
    int lane = threadIdx.x & 31;
    int p    = blockIdx.x * 8 + wid;
    if (p >= M) return;

    float w0 = g_A[0 * C_MLP + lane];
    float w1 = g_A[1 * C_MLP + lane];
    float w2 = g_A[2 * C_MLP + lane];
    float w3 = g_A[3 * C_MLP + lane];
    float w4 = g_A[4 * C_MLP + lane];
    float w5 = g_A[5 * C_MLP + lane];
    float w6 = g_A[6 * C_MLP + lane];
    float w7 = g_A[7 * C_MLP + lane];
    float a8 = g_A[8 * C_MLP + lane];
    float a9 = g_A[9 * C_MLP + lane];
    float e  = g_e[lane];

    int cnt = g_cnt[p];
    if (lane == 0) g_cnt[p] = 0;        // reset for next launch
    if (cnt > CAP) cnt = CAP;

    const float4* pay = g_pay + (size_t)p * CAP * 2;
    float m = __int_as_float(0xff800000);   // -inf

    int j = 0;
    for (; j + 2 <= cnt; j += 2) {
        float4 va0 = __ldg(&pay[2 * j]);
        float4 vb0 = __ldg(&pay[2 * j + 1]);
        float4 va1 = __ldg(&pay[2 * j + 2]);
        float4 vb1 = __ldg(&pay[2 * j + 3]);
        float h0 = va0.x * w0;
        float h1 = va1.x * w0;
        h0 = fmaf(va0.y, w1, h0);  h1 = fmaf(va1.y, w1, h1);
        h0 = fmaf(va0.z, w2, h0);  h1 = fmaf(va1.z, w2, h1);
        h0 = fmaf(va0.w, w3, h0);  h1 = fmaf(va1.w, w3, h1);
        h0 = fmaf(vb0.x, w4, h0);  h1 = fmaf(vb1.x, w4, h1);
        h0 = fmaf(vb0.y, w5, h0);  h1 = fmaf(vb1.y, w5, h1);
        h0 = fmaf(vb0.z, w6, h0);  h1 = fmaf(vb1.z, w6, h1);
        h0 = fmaf(vb0.w, w7, h0);  h1 = fmaf(vb1.w, w7, h1);
        m = fmaxf(m, fmaxf(h0, h1));
    }
    if (j < cnt) {
        float4 va = __ldg(&pay[2 * j]);
        float4 vb = __ldg(&pay[2 * j + 1]);
        float h = va.x * w0;
        h = fmaf(va.y, w1, h);
        h = fmaf(va.z, w2, h);
        h = fmaf(va.w, w3, h);
        h = fmaf(vb.x, w4, h);
        h = fmaf(vb.y, w5, h);
        h = fmaf(vb.z, w6, h);
        h = fmaf(vb.w, w7, h);
        m = fmaxf(m, h);
    }

    float cx = ((float)pil[3 * p + 2] + 0.5f) * PSIZE + XMIN;
    float cy = ((float)pil[3 * p + 1] + 0.5f) * PSIZE + YMIN;
    float d  = fmaf(cx, a8, fmaf(cy, a9, e));
    out[(size_t)p * C_MLP + lane] = fmaxf(m + d, 0.f);
}

// ---------------------------------------------------------------------------
extern "C" void kernel_launch(void* const* d_in, const int* in_sizes, int n_in,
                              void* d_out, int out_size)
{
    const float* xyz   = (const float*)d_in[0];   // (N,3)
    const float* ptf   = (const float*)d_in[1];   // (N,5)
    const float* W1    = (const float*)d_in[2];   // (11,32)
    const float* gamma = (const float*)d_in[3];   // (32)
    const float* beta  = (const float*)d_in[4];   // (32)
    const int*   pil   = (const int*)d_in[5];     // (M,3)
    const int*   psi   = (const int*)d_in[6];     // (N)
    int N = in_sizes[6];
    int M = in_sizes[5] / 3;
    float* out = (float*)d_out;                   // (M,32)

    scatter_kernel<<<(N + 255) / 256, 256>>>(xyz, ptf, psi, N);
    stats_kernel<<<GRID_A, BLK_A>>>(xyz, ptf, pil, psi, N);
    stageB_kernel<<<1, 1024>>>(W1, gamma, beta, N);
    pool_kernel<<<(M + 7) / 8, 256>>>(pil, out, M);
}